// round 7
// baseline (speedup 1.0000x reference)
#include <cuda_runtime.h>
#include <cuda_bf16.h>
#include <cstdint>

#define W 256
#define BH 32
#define NBLOCKS 1024          // 128 images * 8 bands
#define MAGF 516              // floats per mag slot (258 float2)

__device__ float g_partials[NBLOCKS];
__device__ unsigned int g_ticket;   // zero-init; atomicInc wraps after NBLOCKS -> graph-replay safe

// Gaussian taps, computed as numpy does (f64 exp, f64 normalize, cast f32)
constexpr double E2d  = 0.1353352832366127;   // exp(-2)
constexpr double E05d = 0.6065306597126334;   // exp(-0.5)
constexpr double GSUM = 1.0 + 2.0 * (E2d + E05d);
constexpr float  G0 = (float)(E2d / GSUM);
constexpr float  G1 = (float)(E05d / GSUM);
constexpr float  G2 = (float)(1.0 / GSUM);

// Quadrant-exact tangent thresholds for k = 4 + round(atan2(gy,gx)*4/3.14159)
#define TLO_POS 0.414213174f
#define THI_POS 2.414206767f
#define TLO_NEG 0.414216283f
#define THI_NEG 2.414224887f

__device__ __forceinline__ int dir_idx(float gx, float gy) {
    float ax = fabsf(gx), ay = fabsf(gy);
    bool xn = gx < 0.0f;
    float tlo = xn ? TLO_NEG : TLO_POS;
    float thi = xn ? THI_NEG : THI_POS;
    int s = (ay >= ax * tlo) ? ((ay > ax * thi) ? 2 : 1) : 0;
    int kp = xn ? (4 - s) : s;
    int k = (gy < 0.0f) ? (4 - kp) : (4 + kp);
    return k & 7;
}

// NMS neighbor offsets packed in nibbles: (dr+1),(dc+1) per idx (validated rel_err=0)
#define DRP 0x00012221u
#define DCP 0x21000122u

// Operates on SQUARED magnitudes. sqrtf only on pass (rare).
__device__ __forceinline__ float nms_one(float msq, int idx, const float* base, int j) {
    int dr = (int)((DRP >> (idx * 4)) & 3u) - 1;
    int dc = (int)((DCP >> (idx * 4)) & 3u) - 1;
    float np = base[((j + dr) & 3) * MAGF + 2 * dc];
    float nn = base[((j - dr) & 3) * MAGF - 2 * dc];
    bool pass = (fminf(msq - np, msq - nn) > 0.0f) && (msq >= 4.0f);
    return pass ? sqrtf(msq) : 0.0f;
}

// float2 layout everywhere: .x = image0, .y = image1
__global__ __launch_bounds__(256) void canny_fused(const float* __restrict__ in0,
                                                   const float* __restrict__ in1,
                                                   float* __restrict__ out) {
    const int t    = threadIdx.x;           // column
    const int lane = t & 31;
    const int wid  = t >> 5;                // warp = column group of 32
    const int blk  = blockIdx.x;
    const int n    = blk >> 3;              // image
    const int r0   = (blk & 7) * BH;        // band start row (multiple of 32)
    const float* b0 = in0 + n * (W * W) + t;
    const float* b1 = in1 + n * (W * W) + t;

    __shared__ __align__(8) float2 sh_prep[2][W + 4];   // col c -> idx c+2; guards 0,1,258,259
    __shared__ __align__(8) float2 sh_mag[4][W + 2];    // SQUARED mags; col c -> idx c+1
    __shared__ __align__(8) float2 sh_vhalo[2][8][2];   // [slot][warp][0=lane0 val,1=lane31 val]
    __shared__ float  red[256];
    __shared__ double sdd[256];
    __shared__ unsigned s_last;

    // zero everything once (guards stay zero; data cells get overwritten)
    {
        float2 z = make_float2(0.f, 0.f);
        float2* zp = (float2*)sh_prep;
        for (int i = t; i < 2 * (W + 4); i += 256) zp[i] = z;
        float2* zm = (float2*)sh_mag;
        for (int i = t; i < 4 * (W + 2); i += 256) zm[i] = z;
        if (t < 32) ((float2*)sh_vhalo)[t] = z;
    }

    // register rings
    float2 hb0, hb1, hb2, hb3, hb4;                       // hblur rows ir-5..ir-1
    hb0 = hb1 = hb2 = hb3 = hb4 = make_float2(0.f, 0.f);
    float2 v_prev = make_float2(0.f, 0.f);                // vblur of row ir-4
    float2 A0, A1, A2, Bx0, Bx1, Bx2;                     // Sobel row aggregates
    A0 = A1 = A2 = Bx0 = Bx1 = Bx2 = make_float2(0.f, 0.f);
    float2 d1m = make_float2(0.f, 0.f);                   // delayed mag^2
    float2 d2m = make_float2(0.f, 0.f);
    float4 d1g = make_float4(0.f, 0.f, 0.f, 0.f);         // delayed (gx0,gy0,gx1,gy1)
    float4 d2g = make_float4(0.f, 0.f, 0.f, 0.f);
    float acc = 0.f;

    const float* mbase0 = &sh_mag[0][t + 1].x;
    const float* mbase1 = &sh_mag[0][t + 1].y;

    __syncthreads();

    // 44 iterations: ir = r0-5 .. r0+BH+6.  r0 % 4 == 0  ->  ir mod 4 == (j+3) & 3.
    // Pipeline: load ir | hblur ir-1 | vblur ir-3 (regs + halo) | A/B ir-4 (shuffle) |
    //           magsq ir-5 | NMS ir-7.
    #pragma unroll 1
    for (int ir0 = r0 - 5; ir0 < r0 + BH + 7; ir0 += 4) {
        #pragma unroll
        for (int j = 0; j < 4; ++j) {
            const int ir = ir0 + j;
            const int sPrepW = (j + 1) & 1;   // slot for row ir       (ir & 1)
            const int sPrepR = j & 1;         // slot of row ir-1
            const int sHaloW = j & 1;         // slot for vblur row ir-3   ((ir-3) & 1)
            const int sHaloR = (j + 1) & 1;   // slot of vblur row ir-4
            const int sMagW  = (j + 2) & 3;   // slot for row ir-5     ((ir-5) & 3)

            // global prefetch + prep BEFORE the barrier (LDG in flight across it).
            // Prep transform inside the guard: out-of-range rows contribute exact 0.
            float2 p = make_float2(0.f, 0.f);
            if ((unsigned)ir < (unsigned)W) {
                float q0 = b0[ir * W];
                float q1 = b1[ir * W];
                p = make_float2((q0 + 1.0f) * 0.5f, (q1 + 1.0f) * 0.5f);
            }

            __syncthreads();   // single barrier: prior-iter reads | this-iter writes

            sh_prep[sPrepW][t + 2] = p;

            // ---- hblur row ir-1 ----
            {
                const float2* pr = sh_prep[sPrepR];
                float2 a0 = pr[t], a1 = pr[t + 1], a2 = pr[t + 2], a3 = pr[t + 3], a4 = pr[t + 4];
                float2 h;
                h.x = G0 * (a0.x + a4.x) + G1 * (a1.x + a3.x) + G2 * a2.x;
                h.y = G0 * (a0.y + a4.y) + G1 * (a1.y + a3.y) + G2 * a2.y;
                hb0 = hb1; hb1 = hb2; hb2 = hb3; hb3 = hb4; hb4 = h;
            }

            // ---- vblur row br = ir-3 (stays in registers; edges go to halo) ----
            float2 v = make_float2(0.f, 0.f);
            {
                const int br = ir - 3;
                if ((unsigned)br < (unsigned)W) {
                    v.x = G0 * (hb0.x + hb4.x) + G1 * (hb1.x + hb3.x) + G2 * hb2.x;
                    v.y = G0 * (hb0.y + hb4.y) + G1 * (hb1.y + hb3.y) + G2 * hb2.y;
                }
                if (lane == 0)       sh_vhalo[sHaloW][wid][0] = v;
                else if (lane == 31) sh_vhalo[sHaloW][wid][1] = v;
            }

            // ---- Sobel row aggregates for row ir-4 via register exchange ----
            {
                float2 c = v_prev;
                float2 vl, vr;
                vl.x = __shfl_up_sync(0xffffffffu, c.x, 1);
                vl.y = __shfl_up_sync(0xffffffffu, c.y, 1);
                vr.x = __shfl_down_sync(0xffffffffu, c.x, 1);
                vr.y = __shfl_down_sync(0xffffffffu, c.y, 1);
                if (lane == 0)
                    vl = (wid > 0) ? sh_vhalo[sHaloR][wid - 1][1] : make_float2(0.f, 0.f);
                if (lane == 31)
                    vr = (wid < 7) ? sh_vhalo[sHaloR][wid + 1][0] : make_float2(0.f, 0.f);
                float2 A, Bv;
                A.x  = vl.x + 2.0f * c.x + vr.x;   Bv.x = vl.x - vr.x;
                A.y  = vl.y + 2.0f * c.y + vr.y;   Bv.y = vl.y - vr.y;
                A0 = A1; A1 = A2; A2 = A;
                Bx0 = Bx1; Bx1 = Bx2; Bx2 = Bv;
            }
            v_prev = v;

            // ---- Sobel + SQUARED magnitude for row mr = ir-5 (no sqrt, no dir) ----
            float2 nm = make_float2(0.f, 0.f);
            float4 ng = make_float4(0.f, 0.f, 0.f, 0.f);
            {
                const int mr = ir - 5;
                if ((unsigned)mr < (unsigned)W) {
                    ng.x = Bx0.x + 2.0f * Bx1.x + Bx2.x;   // gx0
                    ng.y = A0.x - A2.x;                    // gy0
                    nm.x = ng.x * ng.x + ng.y * ng.y;
                    ng.z = Bx0.y + 2.0f * Bx1.y + Bx2.y;   // gx1
                    ng.w = A0.y - A2.y;                    // gy1
                    nm.y = ng.z * ng.z + ng.w * ng.w;
                }
                sh_mag[sMagW][t + 1] = nm;
            }

            // ---- NMS + threshold + |diff| for row er = ir-7 (er mod 4 == j) ----
            // er <= r0+BH-1 always holds; only lower guard needed. Warp-uniform skip.
            {
                const int er = ir - 7;
                if (er >= r0) {
                    float mx = fmaxf(d2m.x, d2m.y);
                    if (__any_sync(0xffffffffu, mx >= 4.0f)) {
                        int i0 = dir_idx(d2g.x, d2g.y);
                        int i1 = dir_idx(d2g.z, d2g.w);
                        float e0 = nms_one(d2m.x, i0, mbase0, j);
                        float e1 = nms_one(d2m.y, i1, mbase1, j);
                        acc += fabsf(e0 - e1);
                    }
                }
            }

            d2m = d1m; d1m = nm;
            d2g = d1g; d1g = ng;
        }
    }

    // deterministic block reduction
    red[t] = acc;
    __syncthreads();
    #pragma unroll
    for (int off = 128; off > 0; off >>= 1) {
        if (t < off) red[t] += red[t + off];
        __syncthreads();
    }

    if (t == 0) {
        g_partials[blk] = red[0];
        __threadfence();
        unsigned old = atomicInc(&g_ticket, NBLOCKS - 1);   // wraps to 0 -> replay-safe
        s_last = (old == NBLOCKS - 1) ? 1u : 0u;
    }
    __syncthreads();

    // last block deterministically reduces all partials (double precision)
    if (s_last) {
        double s = 0.0;
        for (int i = t; i < NBLOCKS; i += 256) s += (double)__ldcg(&g_partials[i]);
        sdd[t] = s;
        __syncthreads();
        #pragma unroll
        for (int off = 128; off > 0; off >>= 1) {
            if (t < off) sdd[t] += sdd[t + off];
            __syncthreads();
        }
        if (t == 0) out[0] = (float)(sdd[0] / 8388608.0);
    }
}

extern "C" void kernel_launch(void* const* d_in, const int* in_sizes, int n_in,
                              void* d_out, int out_size) {
    const float* gt = (const float*)d_in[0];   // data_input
    const float* pr = (const float*)d_in[1];   // model_output
    canny_fused<<<NBLOCKS, 256>>>(gt, pr, (float*)d_out);
}

// round 8
// speedup vs baseline: 1.5180x; 1.5180x over previous
#include <cuda_runtime.h>
#include <cuda_bf16.h>
#include <cstdint>

#define W 256
#define BH 32
#define NBLOCKS 1024          // 128 images * 8 bands
#define MAGF 516              // floats per mag slot (258 float2)

__device__ float g_partials[NBLOCKS];
__device__ unsigned int g_ticket;   // zero-init; atomicInc wraps after NBLOCKS -> graph-replay safe

// Gaussian taps, computed as numpy does (f64 exp, f64 normalize, cast f32)
constexpr double E2d  = 0.1353352832366127;   // exp(-2)
constexpr double E05d = 0.6065306597126334;   // exp(-0.5)
constexpr double GSUM = 1.0 + 2.0 * (E2d + E05d);
constexpr float  G0 = (float)(E2d / GSUM);
constexpr float  G1 = (float)(E05d / GSUM);
constexpr float  G2 = (float)(1.0 / GSUM);

// Quadrant-exact tangent thresholds for k = 4 + round(atan2(gy,gx)*4/3.14159)
#define TLO_POS 0.414213174f
#define THI_POS 2.414206767f
#define TLO_NEG 0.414216283f
#define THI_NEG 2.414224887f

__device__ __forceinline__ int dir_idx(float gx, float gy) {
    float ax = fabsf(gx), ay = fabsf(gy);
    bool xn = gx < 0.0f;
    float tlo = xn ? TLO_NEG : TLO_POS;
    float thi = xn ? THI_NEG : THI_POS;
    int s = (ay >= ax * tlo) ? ((ay > ax * thi) ? 2 : 1) : 0;
    int kp = xn ? (4 - s) : s;
    int k = (gy < 0.0f) ? (4 - kp) : (4 + kp);
    return k & 7;
}

// NMS neighbor offsets packed in nibbles: (dr+1),(dc+1) per idx (validated rel_err=0)
#define DRP 0x00012221u
#define DCP 0x21000122u

// Squared magnitudes; em8 = er mod 8 (compile-time). sqrtf only on pass (rare).
__device__ __forceinline__ float nms_one(float msq, int idx, const float* base, int em8) {
    int dr = (int)((DRP >> (idx * 4)) & 3u) - 1;
    int dc = (int)((DCP >> (idx * 4)) & 3u) - 1;
    float np = base[((em8 + dr) & 7) * MAGF + 2 * dc];
    float nn = base[((em8 - dr) & 7) * MAGF - 2 * dc];
    bool pass = (fminf(msq - np, msq - nn) > 0.0f) && (msq >= 4.0f);
    return pass ? sqrtf(msq) : 0.0f;
}

// float2 layout everywhere: .x = image0, .y = image1
// TWO ROWS PER BARRIER PERIOD. Period with base row R (even) does:
//   load rows R,R+1 | hblur R-2,R-1 | vblur R-4,R-3 | A/B R-6,R-5 |
//   magsq R-7,R-6 | NMS R-10,R-9.
// All shared reads in a period touch only slots written in EARLIER periods.
__global__ __launch_bounds__(256) void canny_fused(const float* __restrict__ in0,
                                                   const float* __restrict__ in1,
                                                   float* __restrict__ out) {
    const int t   = threadIdx.x;            // column
    const int blk = blockIdx.x;
    const int n   = blk >> 3;               // image
    const int r0  = (blk & 7) * BH;         // band start row (multiple of 32)
    const float* b0 = in0 + n * (W * W) + t;
    const float* b1 = in1 + n * (W * W) + t;

    __shared__ __align__(8) float2 sh_prep[4][W + 4];   // col c -> idx c+2
    __shared__ __align__(8) float2 sh_bl[4][W + 2];     // col c -> idx c+1
    __shared__ __align__(8) float2 sh_mag[8][W + 2];    // SQUARED mags; col c -> idx c+1
    __shared__ float  red[256];
    __shared__ double sdd[256];
    __shared__ unsigned s_last;

    // zero everything once (guard cells stay zero)
    {
        float2 z = make_float2(0.f, 0.f);
        float2* zp = (float2*)sh_prep;
        for (int i = t; i < 4 * (W + 4); i += 256) zp[i] = z;
        float2* zb = (float2*)sh_bl;
        for (int i = t; i < 4 * (W + 2); i += 256) zb[i] = z;
        float2* zm = (float2*)sh_mag;
        for (int i = t; i < 8 * (W + 2); i += 256) zm[i] = z;
    }

    // register rings
    float2 hb0, hb1, hb2, hb3, hb4, hb5;                  // hblur rows R-6..R-1 (post-shift)
    hb0 = hb1 = hb2 = hb3 = hb4 = hb5 = make_float2(0.f, 0.f);
    float2 A0, A1, A2, A3, B0, B1, B2, B3;                // Sobel aggregates rows R-8..R-5
    A0 = A1 = A2 = A3 = B0 = B1 = B2 = B3 = make_float2(0.f, 0.f);
    // delayed NMS inputs: odd row (1 period), even row (2 periods)
    float2 mo  = make_float2(0.f, 0.f);  int dio = 0;
    float2 me1 = make_float2(0.f, 0.f);  int die1 = 0;
    float2 me2 = make_float2(0.f, 0.f);  int die2 = 0;
    float acc = 0.f;

    const float* mbase0 = &sh_mag[0][t + 1].x;
    const float* mbase1 = &sh_mag[0][t + 1].y;

    __syncthreads();

    // 24 periods: R = r0-4 .. r0+42 step 2.  r0 % 32 == 0 -> (r0-4) % 8 == 4,
    // so R mod 8 = (4 + 2*jj) mod 8 is compile-time within the unrolled inner loop.
    #pragma unroll 1
    for (int Rb = r0 - 4; Rb <= r0 + 36; Rb += 8) {
        #pragma unroll
        for (int jj = 0; jj < 4; ++jj) {
            const int R = Rb + 2 * jj;
            const int pW0 = (2 * jj) & 3,     pW1 = (2 * jj + 1) & 3;   // prep write R,R+1
            const int pR0 = (2 * jj + 2) & 3, pR1 = (2 * jj + 3) & 3;   // prep read R-2,R-1
            const int bW0 = (2 * jj) & 3,     bW1 = (2 * jj + 1) & 3;   // bl write R-4,R-3
            const int bR0 = (2 * jj + 2) & 3, bR1 = (2 * jj + 3) & 3;   // bl read R-6,R-5
            const int mW0 = (2 * jj + 5) & 7, mW1 = (2 * jj + 6) & 7;   // mag write R-7,R-6
            const int e0m8 = (2 * jj + 2) & 7;                          // (R-10) mod 8
            const int e1m8 = (2 * jj + 3) & 7;                          // (R-9) mod 8

            // global prefetch + prep for rows R, R+1 BEFORE the barrier.
            // Transform inside the guard: OOB rows contribute exact 0.
            float2 pA = make_float2(0.f, 0.f), pB = make_float2(0.f, 0.f);
            if ((unsigned)R < (unsigned)W) {
                float q0 = b0[R * W], q1 = b1[R * W];
                pA = make_float2((q0 + 1.0f) * 0.5f, (q1 + 1.0f) * 0.5f);
            }
            if ((unsigned)(R + 1) < (unsigned)W) {
                float q0 = b0[(R + 1) * W], q1 = b1[(R + 1) * W];
                pB = make_float2((q0 + 1.0f) * 0.5f, (q1 + 1.0f) * 0.5f);
            }

            __syncthreads();   // one barrier per TWO rows

            sh_prep[pW0][t + 2] = pA;
            sh_prep[pW1][t + 2] = pB;

            // ---- hblur rows R-2, R-1 (prep written last period) ----
            float2 h0, h1;
            {
                const float2* pr = sh_prep[pR0];
                float2 a0 = pr[t], a1 = pr[t + 1], a2 = pr[t + 2], a3 = pr[t + 3], a4 = pr[t + 4];
                h0.x = G0 * (a0.x + a4.x) + G1 * (a1.x + a3.x) + G2 * a2.x;
                h0.y = G0 * (a0.y + a4.y) + G1 * (a1.y + a3.y) + G2 * a2.y;
            }
            {
                const float2* pr = sh_prep[pR1];
                float2 a0 = pr[t], a1 = pr[t + 1], a2 = pr[t + 2], a3 = pr[t + 3], a4 = pr[t + 4];
                h1.x = G0 * (a0.x + a4.x) + G1 * (a1.x + a3.x) + G2 * a2.x;
                h1.y = G0 * (a0.y + a4.y) + G1 * (a1.y + a3.y) + G2 * a2.y;
            }
            hb0 = hb2; hb1 = hb3; hb2 = hb4; hb3 = hb5; hb4 = h0; hb5 = h1;
            // ring now holds rows R-6..R-1

            // ---- vblur rows R-4, R-3 (registers -> sh_bl) ----
            {
                float2 vA = make_float2(0.f, 0.f), vB = make_float2(0.f, 0.f);
                if ((unsigned)(R - 4) < (unsigned)W) {
                    vA.x = G0 * (hb0.x + hb4.x) + G1 * (hb1.x + hb3.x) + G2 * hb2.x;
                    vA.y = G0 * (hb0.y + hb4.y) + G1 * (hb1.y + hb3.y) + G2 * hb2.y;
                }
                if ((unsigned)(R - 3) < (unsigned)W) {
                    vB.x = G0 * (hb1.x + hb5.x) + G1 * (hb2.x + hb4.x) + G2 * hb3.x;
                    vB.y = G0 * (hb1.y + hb5.y) + G1 * (hb2.y + hb4.y) + G2 * hb3.y;
                }
                sh_bl[bW0][t + 1] = vA;
                sh_bl[bW1][t + 1] = vB;
            }

            // ---- Sobel row aggregates rows R-6, R-5 (bl written last period) ----
            {
                float2 An0, Bn0, An1, Bn1;
                {
                    const float2* bl = sh_bl[bR0];
                    float2 l = bl[t], c = bl[t + 1], r = bl[t + 2];
                    An0.x = l.x + 2.0f * c.x + r.x;  Bn0.x = l.x - r.x;
                    An0.y = l.y + 2.0f * c.y + r.y;  Bn0.y = l.y - r.y;
                }
                {
                    const float2* bl = sh_bl[bR1];
                    float2 l = bl[t], c = bl[t + 1], r = bl[t + 2];
                    An1.x = l.x + 2.0f * c.x + r.x;  Bn1.x = l.x - r.x;
                    An1.y = l.y + 2.0f * c.y + r.y;  Bn1.y = l.y - r.y;
                }
                A0 = A2; A1 = A3; A2 = An0; A3 = An1;
                B0 = B2; B1 = B3; B2 = Bn0; B3 = Bn1;
                // rings now hold rows R-8..R-5
            }

            // ---- magsq rows R-7 (odd), R-6 (even); dir packed under warp-any skip ----
            float2 nm7 = make_float2(0.f, 0.f), nm6 = make_float2(0.f, 0.f);
            int di7 = 0, di6 = 0;
            if ((unsigned)(R - 7) < (unsigned)W) {
                float gx0 = B0.x + 2.0f * B1.x + B2.x, gy0 = A0.x - A2.x;
                float gx1 = B0.y + 2.0f * B1.y + B2.y, gy1 = A0.y - A2.y;
                nm7.x = gx0 * gx0 + gy0 * gy0;
                nm7.y = gx1 * gx1 + gy1 * gy1;
                if (__any_sync(0xffffffffu, fmaxf(nm7.x, nm7.y) >= 4.0f))
                    di7 = dir_idx(gx0, gy0) | (dir_idx(gx1, gy1) << 4);
            }
            if ((unsigned)(R - 6) < (unsigned)W) {
                float gx0 = B1.x + 2.0f * B2.x + B3.x, gy0 = A1.x - A3.x;
                float gx1 = B1.y + 2.0f * B2.y + B3.y, gy1 = A1.y - A3.y;
                nm6.x = gx0 * gx0 + gy0 * gy0;
                nm6.y = gx1 * gx1 + gy1 * gy1;
                if (__any_sync(0xffffffffu, fmaxf(nm6.x, nm6.y) >= 4.0f))
                    di6 = dir_idx(gx0, gy0) | (dir_idx(gx1, gy1) << 4);
            }
            sh_mag[mW0][t + 1] = nm7;
            sh_mag[mW1][t + 1] = nm6;

            // ---- NMS rows er0 = R-10 (uses me2), er1 = R-9 (uses mo) ----
            {
                const int er0 = R - 10;
                if (er0 >= r0 && er0 < r0 + BH) {
                    if (__any_sync(0xffffffffu, fmaxf(me2.x, me2.y) >= 4.0f)) {
                        float e0 = nms_one(me2.x, die2 & 7,        mbase0, e0m8);
                        float e1 = nms_one(me2.y, (die2 >> 4) & 7, mbase1, e0m8);
                        acc += fabsf(e0 - e1);
                    }
                }
                const int er1 = R - 9;
                if (er1 >= r0 && er1 < r0 + BH) {
                    if (__any_sync(0xffffffffu, fmaxf(mo.x, mo.y) >= 4.0f)) {
                        float e0 = nms_one(mo.x, dio & 7,        mbase0, e1m8);
                        float e1 = nms_one(mo.y, (dio >> 4) & 7, mbase1, e1m8);
                        acc += fabsf(e0 - e1);
                    }
                }
            }

            // advance delays: even row 2 periods, odd row 1 period
            me2 = me1; die2 = die1;
            me1 = nm6; die1 = di6;
            mo  = nm7; dio  = di7;
        }
    }

    // deterministic block reduction
    red[t] = acc;
    __syncthreads();
    #pragma unroll
    for (int off = 128; off > 0; off >>= 1) {
        if (t < off) red[t] += red[t + off];
        __syncthreads();
    }

    if (t == 0) {
        g_partials[blk] = red[0];
        __threadfence();
        unsigned old = atomicInc(&g_ticket, NBLOCKS - 1);   // wraps to 0 -> replay-safe
        s_last = (old == NBLOCKS - 1) ? 1u : 0u;
    }
    __syncthreads();

    // last block deterministically reduces all partials (double precision)
    if (s_last) {
        double s = 0.0;
        for (int i = t; i < NBLOCKS; i += 256) s += (double)__ldcg(&g_partials[i]);
        sdd[t] = s;
        __syncthreads();
        #pragma unroll
        for (int off = 128; off > 0; off >>= 1) {
            if (t < off) sdd[t] += sdd[t + off];
            __syncthreads();
        }
        if (t == 0) out[0] = (float)(sdd[0] / 8388608.0);
    }
}

extern "C" void kernel_launch(void* const* d_in, const int* in_sizes, int n_in,
                              void* d_out, int out_size) {
    const float* gt = (const float*)d_in[0];   // data_input
    const float* pr = (const float*)d_in[1];   // model_output
    canny_fused<<<NBLOCKS, 256>>>(gt, pr, (float*)d_out);
}

// round 9
// speedup vs baseline: 1.7154x; 1.1300x over previous
#include <cuda_runtime.h>
#include <cuda_bf16.h>
#include <cstdint>

#define W 256
#define BH 64
#define NBLOCKS 512           // 128 images * 4 bands
#define MAGF 516              // floats per mag slot (258 float2)

__device__ float g_partials[NBLOCKS];
__device__ unsigned int g_ticket;   // zero-init; atomicInc wraps after NBLOCKS -> graph-replay safe

// Gaussian taps, computed as numpy does (f64 exp, f64 normalize, cast f32)
constexpr double E2d  = 0.1353352832366127;   // exp(-2)
constexpr double E05d = 0.6065306597126334;   // exp(-0.5)
constexpr double GSUM = 1.0 + 2.0 * (E2d + E05d);
constexpr float  G0 = (float)(E2d / GSUM);
constexpr float  G1 = (float)(E05d / GSUM);
constexpr float  G2 = (float)(1.0 / GSUM);

// Quadrant-exact tangent thresholds for k = 4 + round(atan2(gy,gx)*4/3.14159)
#define TLO_POS 0.414213174f
#define THI_POS 2.414206767f
#define TLO_NEG 0.414216283f
#define THI_NEG 2.414224887f

__device__ __forceinline__ int dir_idx(float gx, float gy) {
    float ax = fabsf(gx), ay = fabsf(gy);
    bool xn = gx < 0.0f;
    float tlo = xn ? TLO_NEG : TLO_POS;
    float thi = xn ? THI_NEG : THI_POS;
    int s = (ay >= ax * tlo) ? ((ay > ax * thi) ? 2 : 1) : 0;
    int kp = xn ? (4 - s) : s;
    int k = (gy < 0.0f) ? (4 - kp) : (4 + kp);
    return k & 7;
}

// NMS neighbor offsets packed in nibbles: (dr+1),(dc+1) per idx (validated rel_err=0)
#define DRP 0x00012221u
#define DCP 0x21000122u

// Operates on SQUARED magnitudes. sqrtf only on pass (rare).
__device__ __forceinline__ float nms_one(float msq, int idx, const float* base, int j) {
    int dr = (int)((DRP >> (idx * 4)) & 3u) - 1;
    int dc = (int)((DCP >> (idx * 4)) & 3u) - 1;
    float np = base[((j + dr) & 3) * MAGF + 2 * dc];
    float nn = base[((j - dr) & 3) * MAGF - 2 * dc];
    bool pass = (fminf(msq - np, msq - nn) > 0.0f) && (msq >= 4.0f);
    return pass ? sqrtf(msq) : 0.0f;
}

// float2 layout everywhere: .x = image0, .y = image1
__global__ __launch_bounds__(256, 4) void canny_fused(const float* __restrict__ in0,
                                                      const float* __restrict__ in1,
                                                      float* __restrict__ out) {
    const int t   = threadIdx.x;            // column
    const int blk = blockIdx.x;
    const int n   = blk >> 2;               // image
    const int r0  = (blk & 3) * BH;         // band start row (multiple of 64)
    const float* b0 = in0 + n * (W * W) + t;
    const float* b1 = in1 + n * (W * W) + t;

    __shared__ __align__(8) float2 sh_prep[2][W + 4];   // col c -> idx c+2; guards 0,1,258,259
    __shared__ __align__(8) float2 sh_bl[2][W + 2];     // col c -> idx c+1; guards 0,257
    __shared__ __align__(8) float2 sh_mag[4][W + 2];    // SQUARED mags; col c -> idx c+1
    __shared__ float  red[256];
    __shared__ double sdd[256];
    __shared__ unsigned s_last;

    // zero everything once (guards stay zero; data cells get overwritten)
    {
        float2 z = make_float2(0.f, 0.f);
        float2* zp = (float2*)sh_prep;
        for (int i = t; i < 2 * (W + 4); i += 256) zp[i] = z;
        float2* zb = (float2*)sh_bl;
        for (int i = t; i < 2 * (W + 2); i += 256) zb[i] = z;
        float2* zm = (float2*)sh_mag;
        for (int i = t; i < 4 * (W + 2); i += 256) zm[i] = z;
    }

    // register rings
    float2 hb0, hb1, hb2, hb3, hb4;                       // hblur rows ir-5..ir-1
    hb0 = hb1 = hb2 = hb3 = hb4 = make_float2(0.f, 0.f);
    float2 A0, A1, A2, Bx0, Bx1, Bx2;                     // Sobel row aggregates
    A0 = A1 = A2 = Bx0 = Bx1 = Bx2 = make_float2(0.f, 0.f);
    float2 p_prev = make_float2(0.f, 0.f);                // own prep value (hblur center tap)
    float2 v_prev = make_float2(0.f, 0.f);                // own vblur value (A/B center tap)
    float2 d1m = make_float2(0.f, 0.f);                   // delayed mag^2
    float2 d2m = make_float2(0.f, 0.f);
    int d1i = 0, d2i = 0;                                 // packed 2x4-bit dir indices
    float acc = 0.f;

    const float* mbase0 = &sh_mag[0][t + 1].x;
    const float* mbase1 = &sh_mag[0][t + 1].y;

    __syncthreads();

    // 76 iterations: ir = r0-5 .. r0+BH+6.  r0 % 4 == 0  ->  ir mod 4 == (j+3) & 3.
    // Pipeline: load ir | hblur ir-1 | vblur ir-3 | A/B ir-4 | magsq ir-5 | NMS ir-7.
    #pragma unroll 1
    for (int ir0 = r0 - 5; ir0 < r0 + BH + 7; ir0 += 4) {
        #pragma unroll
        for (int j = 0; j < 4; ++j) {
            const int ir = ir0 + j;
            const int sPrepW = (j + 1) & 1;   // slot for row ir       (ir & 1)
            const int sPrepR = j & 1;         // slot of row ir-1
            const int sBlW   = j & 1;         // slot for row ir-3     ((ir-3) & 1)
            const int sBlR   = (j + 1) & 1;   // slot of row ir-4
            const int sMagW  = (j + 2) & 3;   // slot for row ir-5     ((ir-5) & 3)

            // global prefetch + prep BEFORE the barrier (LDG in flight across it).
            // Prep transform inside the guard: out-of-range rows contribute exact 0.
            float2 p = make_float2(0.f, 0.f);
            if ((unsigned)ir < (unsigned)W) {
                float q0 = b0[ir * W];
                float q1 = b1[ir * W];
                p = make_float2((q0 + 1.0f) * 0.5f, (q1 + 1.0f) * 0.5f);
            }

            __syncthreads();   // single barrier: prior-iter reads | this-iter writes

            sh_prep[sPrepW][t + 2] = p;

            // ---- hblur row ir-1 (center tap from register p_prev) ----
            {
                const float2* pr = sh_prep[sPrepR];
                float2 a0 = pr[t], a1 = pr[t + 1], a3 = pr[t + 3], a4 = pr[t + 4];
                float2 a2 = p_prev;
                float2 h;
                h.x = G0 * (a0.x + a4.x) + G1 * (a1.x + a3.x) + G2 * a2.x;
                h.y = G0 * (a0.y + a4.y) + G1 * (a1.y + a3.y) + G2 * a2.y;
                hb0 = hb1; hb1 = hb2; hb2 = hb3; hb3 = hb4; hb4 = h;
            }
            p_prev = p;

            // ---- vblur row br = ir-3 ----
            float2 v = make_float2(0.f, 0.f);
            {
                const int br = ir - 3;
                if ((unsigned)br < (unsigned)W) {
                    v.x = G0 * (hb0.x + hb4.x) + G1 * (hb1.x + hb3.x) + G2 * hb2.x;
                    v.y = G0 * (hb0.y + hb4.y) + G1 * (hb1.y + hb3.y) + G2 * hb2.y;
                }
                sh_bl[sBlW][t + 1] = v;
            }

            // ---- Sobel row aggregates for row ir-4 (center tap from register v_prev) ----
            {
                const float2* bl = sh_bl[sBlR];
                float2 l = bl[t], r = bl[t + 2];
                float2 c = v_prev;
                float2 A, Bv;
                A.x  = l.x + 2.0f * c.x + r.x;   Bv.x = l.x - r.x;
                A.y  = l.y + 2.0f * c.y + r.y;   Bv.y = l.y - r.y;
                A0 = A1; A1 = A2; A2 = A;
                Bx0 = Bx1; Bx1 = Bx2; Bx2 = Bv;
            }
            v_prev = v;

            // ---- Sobel + SQUARED magnitude for row mr = ir-5; dir packed under skip ----
            float2 nm = make_float2(0.f, 0.f);
            int ni = 0;
            {
                const int mr = ir - 5;
                if ((unsigned)mr < (unsigned)W) {
                    float gx0 = Bx0.x + 2.0f * Bx1.x + Bx2.x;
                    float gy0 = A0.x - A2.x;
                    nm.x = gx0 * gx0 + gy0 * gy0;
                    float gx1 = Bx0.y + 2.0f * Bx1.y + Bx2.y;
                    float gy1 = A0.y - A2.y;
                    nm.y = gx1 * gx1 + gy1 * gy1;
                    if (__any_sync(0xffffffffu, fmaxf(nm.x, nm.y) >= 4.0f))
                        ni = dir_idx(gx0, gy0) | (dir_idx(gx1, gy1) << 4);
                }
                sh_mag[sMagW][t + 1] = nm;
            }

            // ---- NMS + threshold + |diff| for row er = ir-7 (er mod 4 == j) ----
            {
                const int er = ir - 7;
                if (er >= r0) {   // er <= r0+BH-1 always
                    if (__any_sync(0xffffffffu, fmaxf(d2m.x, d2m.y) >= 4.0f)) {
                        float e0 = nms_one(d2m.x, d2i & 7,        mbase0, j);
                        float e1 = nms_one(d2m.y, (d2i >> 4) & 7, mbase1, j);
                        acc += fabsf(e0 - e1);
                    }
                }
            }

            d2m = d1m; d1m = nm;
            d2i = d1i; d1i = ni;
        }
    }

    // deterministic block reduction
    red[t] = acc;
    __syncthreads();
    #pragma unroll
    for (int off = 128; off > 0; off >>= 1) {
        if (t < off) red[t] += red[t + off];
        __syncthreads();
    }

    if (t == 0) {
        g_partials[blk] = red[0];
        __threadfence();
        unsigned old = atomicInc(&g_ticket, NBLOCKS - 1);   // wraps to 0 -> replay-safe
        s_last = (old == NBLOCKS - 1) ? 1u : 0u;
    }
    __syncthreads();

    // last block deterministically reduces all partials (double precision)
    if (s_last) {
        double s = 0.0;
        for (int i = t; i < NBLOCKS; i += 256) s += (double)__ldcg(&g_partials[i]);
        sdd[t] = s;
        __syncthreads();
        #pragma unroll
        for (int off = 128; off > 0; off >>= 1) {
            if (t < off) sdd[t] += sdd[t + off];
            __syncthreads();
        }
        if (t == 0) out[0] = (float)(sdd[0] / 8388608.0);
    }
}

extern "C" void kernel_launch(void* const* d_in, const int* in_sizes, int n_in,
                              void* d_out, int out_size) {
    const float* gt = (const float*)d_in[0];   // data_input
    const float* pr = (const float*)d_in[1];   // model_output
    canny_fused<<<NBLOCKS, 256>>>(gt, pr, (float*)d_out);
}

// round 10
// speedup vs baseline: 1.7255x; 1.0059x over previous
#include <cuda_runtime.h>
#include <cuda_bf16.h>
#include <cstdint>

#define W 256
#define BH 64
#define NBLOCKS 512           // 128 images * 4 bands
#define MAGF 516              // floats per mag slot (258 float2)

__device__ float g_partials[NBLOCKS];
__device__ unsigned int g_ticket;   // zero-init; atomicInc wraps after NBLOCKS -> graph-replay safe

// Gaussian taps, computed as numpy does (f64 exp, f64 normalize, cast f32)
constexpr double E2d  = 0.1353352832366127;   // exp(-2)
constexpr double E05d = 0.6065306597126334;   // exp(-0.5)
constexpr double GSUM = 1.0 + 2.0 * (E2d + E05d);
constexpr float  G0 = (float)(E2d / GSUM);
constexpr float  G1 = (float)(E05d / GSUM);
constexpr float  G2 = (float)(1.0 / GSUM);

// Quadrant-exact tangent thresholds for k = 4 + round(atan2(gy,gx)*4/3.14159)
#define TLO_POS 0.414213174f
#define THI_POS 2.414206767f
#define TLO_NEG 0.414216283f
#define THI_NEG 2.414224887f

__device__ __forceinline__ int dir_idx(float gx, float gy) {
    float ax = fabsf(gx), ay = fabsf(gy);
    bool xn = gx < 0.0f;
    float tlo = xn ? TLO_NEG : TLO_POS;
    float thi = xn ? THI_NEG : THI_POS;
    int s = (ay >= ax * tlo) ? ((ay > ax * thi) ? 2 : 1) : 0;
    int kp = xn ? (4 - s) : s;
    int k = (gy < 0.0f) ? (4 - kp) : (4 + kp);
    return k & 7;
}

// NMS neighbor offsets packed in nibbles: (dr+1),(dc+1) per idx (validated rel_err=0)
#define DRP 0x00012221u
#define DCP 0x21000122u

// Operates on SQUARED magnitudes. sqrtf only on pass (rare).
__device__ __forceinline__ float nms_one(float msq, int idx, const float* base, int j) {
    int dr = (int)((DRP >> (idx * 4)) & 3u) - 1;
    int dc = (int)((DCP >> (idx * 4)) & 3u) - 1;
    float np = base[((j + dr) & 3) * MAGF + 2 * dc];
    float nn = base[((j - dr) & 3) * MAGF - 2 * dc];
    bool pass = (fminf(msq - np, msq - nn) > 0.0f) && (msq >= 4.0f);
    return pass ? sqrtf(msq) : 0.0f;
}

// float2 layout everywhere: .x = image0, .y = image1
__global__ __launch_bounds__(256, 4) void canny_fused(const float* __restrict__ in0,
                                                      const float* __restrict__ in1,
                                                      float* __restrict__ out) {
    const int t   = threadIdx.x;            // column
    const int blk = blockIdx.x;
    const int n   = blk >> 2;               // image
    const int r0  = (blk & 3) * BH;         // band start row (multiple of 64)
    const float* b0 = in0 + n * (W * W) + t;
    const float* b1 = in1 + n * (W * W) + t;

    __shared__ __align__(8) float2 sh_prep[2][W + 4];   // col c -> idx c+2; guards 0,1,258,259
    __shared__ __align__(8) float2 sh_bl[2][W + 2];     // col c -> idx c+1; guards 0,257
    __shared__ __align__(8) float2 sh_mag[4][W + 2];    // SQUARED mags; col c -> idx c+1
    __shared__ float  red[256];
    __shared__ double sdd[256];
    __shared__ unsigned s_last;

    // zero everything once (guards stay zero; data cells get overwritten)
    {
        float2 z = make_float2(0.f, 0.f);
        float2* zp = (float2*)sh_prep;
        for (int i = t; i < 2 * (W + 4); i += 256) zp[i] = z;
        float2* zb = (float2*)sh_bl;
        for (int i = t; i < 2 * (W + 2); i += 256) zb[i] = z;
        float2* zm = (float2*)sh_mag;
        for (int i = t; i < 4 * (W + 2); i += 256) zm[i] = z;
    }

    // register rings
    float2 hb0, hb1, hb2, hb3, hb4;                       // hblur rows ir-5..ir-1
    hb0 = hb1 = hb2 = hb3 = hb4 = make_float2(0.f, 0.f);
    float2 A0, A1, A2, Bx0, Bx1, Bx2;                     // Sobel row aggregates
    A0 = A1 = A2 = Bx0 = Bx1 = Bx2 = make_float2(0.f, 0.f);
    float2 p_prev = make_float2(0.f, 0.f);                // own prep value (hblur center tap)
    float2 v_prev = make_float2(0.f, 0.f);                // own vblur value (A/B center tap)
    float2 d1m = make_float2(0.f, 0.f);                   // delayed mag^2
    float2 d2m = make_float2(0.f, 0.f);
    int d1i = 0, d2i = 0;                                 // packed 2x4-bit dir indices
    float acc = 0.f;

    const float* mbase0 = &sh_mag[0][t + 1].x;
    const float* mbase1 = &sh_mag[0][t + 1].y;

    // software prefetch: raw row values for the CURRENT iteration, loaded one
    // iteration in advance (one full iteration of latency hiding for the DRAM miss).
    float qa0 = 0.f, qa1 = 0.f;
    {
        const int irf = r0 - 5;
        if ((unsigned)irf < (unsigned)W) {
            qa0 = b0[irf * W];
            qa1 = b1[irf * W];
        }
    }

    __syncthreads();

    // 76 iterations: ir = r0-5 .. r0+BH+6.  r0 % 4 == 0  ->  ir mod 4 == (j+3) & 3.
    // Pipeline: load ir+1 (prefetch) | hblur ir-1 | vblur ir-3 | A/B ir-4 |
    //           magsq ir-5 | NMS ir-7.
    #pragma unroll 1
    for (int ir0 = r0 - 5; ir0 < r0 + BH + 7; ir0 += 4) {
        #pragma unroll
        for (int j = 0; j < 4; ++j) {
            const int ir = ir0 + j;
            const int sPrepW = (j + 1) & 1;   // slot for row ir       (ir & 1)
            const int sPrepR = j & 1;         // slot of row ir-1
            const int sBlW   = j & 1;         // slot for row ir-3     ((ir-3) & 1)
            const int sBlR   = (j + 1) & 1;   // slot of row ir-4
            const int sMagW  = (j + 2) & 3;   // slot for row ir-5     ((ir-5) & 3)

            // ---- prefetch row ir+1 (consumed NEXT iteration -> DRAM latency hidden) ----
            float qb0 = 0.f, qb1 = 0.f;
            {
                const int irn = ir + 1;
                if ((unsigned)irn < (unsigned)W) {
                    qb0 = b0[irn * W];
                    qb1 = b1[irn * W];
                }
            }

            __syncthreads();   // single barrier: prior-iter reads | this-iter writes

            // prep of row ir from the PREVIOUSLY prefetched values.
            // Transform inside the guard: out-of-range rows contribute exact 0.
            float2 p = make_float2(0.f, 0.f);
            if ((unsigned)ir < (unsigned)W)
                p = make_float2((qa0 + 1.0f) * 0.5f, (qa1 + 1.0f) * 0.5f);
            sh_prep[sPrepW][t + 2] = p;

            // ---- hblur row ir-1 (center tap from register p_prev) ----
            {
                const float2* pr = sh_prep[sPrepR];
                float2 a0 = pr[t], a1 = pr[t + 1], a3 = pr[t + 3], a4 = pr[t + 4];
                float2 a2 = p_prev;
                float2 h;
                h.x = G0 * (a0.x + a4.x) + G1 * (a1.x + a3.x) + G2 * a2.x;
                h.y = G0 * (a0.y + a4.y) + G1 * (a1.y + a3.y) + G2 * a2.y;
                hb0 = hb1; hb1 = hb2; hb2 = hb3; hb3 = hb4; hb4 = h;
            }
            p_prev = p;

            // ---- vblur row br = ir-3 ----
            float2 v = make_float2(0.f, 0.f);
            {
                const int br = ir - 3;
                if ((unsigned)br < (unsigned)W) {
                    v.x = G0 * (hb0.x + hb4.x) + G1 * (hb1.x + hb3.x) + G2 * hb2.x;
                    v.y = G0 * (hb0.y + hb4.y) + G1 * (hb1.y + hb3.y) + G2 * hb2.y;
                }
                sh_bl[sBlW][t + 1] = v;
            }

            // ---- Sobel row aggregates for row ir-4 (center tap from register v_prev) ----
            {
                const float2* bl = sh_bl[sBlR];
                float2 l = bl[t], r = bl[t + 2];
                float2 c = v_prev;
                float2 A, Bv;
                A.x  = l.x + 2.0f * c.x + r.x;   Bv.x = l.x - r.x;
                A.y  = l.y + 2.0f * c.y + r.y;   Bv.y = l.y - r.y;
                A0 = A1; A1 = A2; A2 = A;
                Bx0 = Bx1; Bx1 = Bx2; Bx2 = Bv;
            }
            v_prev = v;

            // ---- Sobel + SQUARED magnitude for row mr = ir-5; dir packed under skip ----
            float2 nm = make_float2(0.f, 0.f);
            int ni = 0;
            {
                const int mr = ir - 5;
                if ((unsigned)mr < (unsigned)W) {
                    float gx0 = Bx0.x + 2.0f * Bx1.x + Bx2.x;
                    float gy0 = A0.x - A2.x;
                    nm.x = gx0 * gx0 + gy0 * gy0;
                    float gx1 = Bx0.y + 2.0f * Bx1.y + Bx2.y;
                    float gy1 = A0.y - A2.y;
                    nm.y = gx1 * gx1 + gy1 * gy1;
                    if (__any_sync(0xffffffffu, fmaxf(nm.x, nm.y) >= 4.0f))
                        ni = dir_idx(gx0, gy0) | (dir_idx(gx1, gy1) << 4);
                }
                sh_mag[sMagW][t + 1] = nm;
            }

            // ---- NMS + threshold + |diff| for row er = ir-7 (er mod 4 == j) ----
            {
                const int er = ir - 7;
                if (er >= r0) {   // er <= r0+BH-1 always
                    if (__any_sync(0xffffffffu, fmaxf(d2m.x, d2m.y) >= 4.0f)) {
                        float e0 = nms_one(d2m.x, d2i & 7,        mbase0, j);
                        float e1 = nms_one(d2m.y, (d2i >> 4) & 7, mbase1, j);
                        acc += fabsf(e0 - e1);
                    }
                }
            }

            d2m = d1m; d1m = nm;
            d2i = d1i; d1i = ni;
            qa0 = qb0; qa1 = qb1;
        }
    }

    // deterministic block reduction
    red[t] = acc;
    __syncthreads();
    #pragma unroll
    for (int off = 128; off > 0; off >>= 1) {
        if (t < off) red[t] += red[t + off];
        __syncthreads();
    }

    if (t == 0) {
        g_partials[blk] = red[0];
        __threadfence();
        unsigned old = atomicInc(&g_ticket, NBLOCKS - 1);   // wraps to 0 -> replay-safe
        s_last = (old == NBLOCKS - 1) ? 1u : 0u;
    }
    __syncthreads();

    // last block deterministically reduces all partials (double precision)
    if (s_last) {
        double s = 0.0;
        for (int i = t; i < NBLOCKS; i += 256) s += (double)__ldcg(&g_partials[i]);
        sdd[t] = s;
        __syncthreads();
        #pragma unroll
        for (int off = 128; off > 0; off >>= 1) {
            if (t < off) sdd[t] += sdd[t + off];
            __syncthreads();
        }
        if (t == 0) out[0] = (float)(sdd[0] / 8388608.0);
    }
}

extern "C" void kernel_launch(void* const* d_in, const int* in_sizes, int n_in,
                              void* d_out, int out_size) {
    const float* gt = (const float*)d_in[0];   // data_input
    const float* pr = (const float*)d_in[1];   // model_output
    canny_fused<<<NBLOCKS, 256>>>(gt, pr, (float*)d_out);
}